// round 4
// baseline (speedup 1.0000x reference)
#include <cuda_runtime.h>
#include <cuda_bf16.h>

// emb = ((mask @ h) @ W2 + counts*b2) / max(counts,1),  h = relu(idx@W1+b1) [S,16]
//
// Warp-per-row, two-stage per 256-scene chunk:
//   compact: ballot + prefix-popc writes nonzero scene indices into per-warp smem
//   consume: 8 lane-groups of 4 lanes; each group services one index per
//            iteration with a single LDS.128 (4 dims/lane) -> 8 nz/iteration.
// Epilogue: butterfly-reduce float4 accumulators, 16->128 via W2 (LDS.128/STG.128).

#define S        2000
#define SV4      500
#define HDIM     16
#define HSTRIDE  20            // float4-aligned; 20*s mod 32 spreads rows over banks
#define EDIM     128
#define THREADS  1024
#define WARPS    32
#define CAP      256           // per-warp index buffer (= chunk scene count)
#define NCHUNK   8             // 8 chunks x 2 float4-groups (256 scenes)

__device__ float g_h[S * HDIM];

__global__ void build_h_kernel(const float* __restrict__ W1,
                               const float* __restrict__ b1) {
    int i = blockIdx.x * blockDim.x + threadIdx.x;
    if (i < S * HDIM) {
        int s = i >> 4;
        int d = i & 15;
        float v = fmaf((float)s, W1[d], b1[d]);
        g_h[i] = v > 0.0f ? v : 0.0f;
    }
}

__global__ void __launch_bounds__(THREADS, 1)
embed_kernel(const float* __restrict__ m,
             const float* __restrict__ W2,
             const float* __restrict__ b2,
             float* __restrict__ out,
             int L) {
    extern __shared__ float sm[];
    float* hs  = sm;                              // S * HSTRIDE
    float* w2s = sm + S * HSTRIDE;                // HDIM * EDIM
    float* b2s = w2s + HDIM * EDIM;               // EDIM
    unsigned* sidx_all = (unsigned*)(b2s + EDIM); // WARPS * CAP

    for (int i = threadIdx.x; i < S * HDIM; i += THREADS) {
        int s = i >> 4, d = i & 15;
        hs[s * HSTRIDE + d] = g_h[i];
    }
    for (int i = threadIdx.x; i < HDIM * EDIM; i += THREADS) w2s[i] = W2[i];
    for (int i = threadIdx.x; i < EDIM; i += THREADS) b2s[i] = b2[i];
    __syncthreads();

    const int wid  = threadIdx.x >> 5;
    const int lane = threadIdx.x & 31;
    const int g8   = lane >> 2;        // lane-group 0..7: which index to service
    const int d4   = lane & 3;         // float4 slice of the h row
    const unsigned ltm = (1u << lane) - 1u;
    unsigned* sidx = sidx_all + wid * CAP;
    const int warpsTotal = gridDim.x * WARPS;

    for (int row = blockIdx.x * WARPS + wid; row < L; row += warpsTotal) {
        const float4* row4 = reinterpret_cast<const float4*>(m + (size_t)row * S);
        float4 acc = make_float4(0.f, 0.f, 0.f, 0.f);
        int count = 0;

        float4 vcur = __ldg(&row4[lane]);   // group 0 always in range

        #pragma unroll
        for (int c = 0; c < NCHUNK; c++) {
            int cnt = 0;
            #pragma unroll
            for (int u = 0; u < 2; u++) {
                const int g = 2 * c + u;
                float4 v = vcur;
                if (g + 1 < 16) {
                    int ni = (g + 1) * 32 + lane;
                    float4 vn = make_float4(0.f, 0.f, 0.f, 0.f);
                    if (ni < SV4) vn = __ldg(&row4[ni]);
                    vcur = vn;
                }
                const int sbase = g * 128 + 4 * lane;
                #pragma unroll
                for (int e = 0; e < 4; e++) {
                    float comp = (e == 0) ? v.x : (e == 1) ? v.y
                               : (e == 2) ? v.z : v.w;
                    bool nz = (comp != 0.0f);
                    unsigned be = __ballot_sync(0xffffffffu, nz);
                    if (nz) sidx[cnt + __popc(be & ltm)] = sbase + e;
                    cnt += __popc(be);
                }
            }
            count += cnt;
            __syncwarp();
            for (int i = g8; i < cnt; i += 8) {
                int scene = (int)sidx[i];
                const float4 hv = *reinterpret_cast<const float4*>(
                    &hs[scene * HSTRIDE + 4 * d4]);
                acc.x += hv.x; acc.y += hv.y; acc.z += hv.z; acc.w += hv.w;
            }
            __syncwarp();
        }

        // reduce across the 8 lane-groups; dims land on lanes 0..3
        #pragma unroll
        for (int ofs = 4; ofs <= 16; ofs <<= 1) {
            acc.x += __shfl_xor_sync(0xffffffffu, acc.x, ofs);
            acc.y += __shfl_xor_sync(0xffffffffu, acc.y, ofs);
            acc.z += __shfl_xor_sync(0xffffffffu, acc.z, ofs);
            acc.w += __shfl_xor_sync(0xffffffffu, acc.w, ofs);
        }

        // broadcast the 16 dim totals (lane k holds dims 4k..4k+3)
        float a[HDIM];
        #pragma unroll
        for (int k = 0; k < 4; k++) {
            a[4 * k + 0] = __shfl_sync(0xffffffffu, acc.x, k);
            a[4 * k + 1] = __shfl_sync(0xffffffffu, acc.y, k);
            a[4 * k + 2] = __shfl_sync(0xffffffffu, acc.z, k);
            a[4 * k + 3] = __shfl_sync(0xffffffffu, acc.w, k);
        }

        float cntf = (float)count;
        float inv = 1.0f / fmaxf(cntf, 1.0f);

        const float4 bv = *reinterpret_cast<const float4*>(&b2s[4 * lane]);
        float4 s = make_float4(cntf * bv.x, cntf * bv.y, cntf * bv.z, cntf * bv.w);
        #pragma unroll
        for (int dd = 0; dd < HDIM; dd++) {
            const float4 wv = *reinterpret_cast<const float4*>(
                &w2s[dd * EDIM + 4 * lane]);
            s.x = fmaf(a[dd], wv.x, s.x);
            s.y = fmaf(a[dd], wv.y, s.y);
            s.z = fmaf(a[dd], wv.z, s.z);
            s.w = fmaf(a[dd], wv.w, s.w);
        }
        s.x *= inv; s.y *= inv; s.z *= inv; s.w *= inv;
        *reinterpret_cast<float4*>(out + (size_t)row * EDIM + 4 * lane) = s;
    }
}

extern "C" void kernel_launch(void* const* d_in, const int* in_sizes, int n_in,
                              void* d_out, int out_size) {
    const float* m  = (const float*)d_in[0];
    const float* W1 = (const float*)d_in[1];
    const float* b1 = (const float*)d_in[2];
    const float* W2 = (const float*)d_in[3];
    const float* b2 = (const float*)d_in[4];
    float* out = (float*)d_out;

    int L = in_sizes[0] / S;

    build_h_kernel<<<(S * HDIM + 255) / 256, 256>>>(W1, b1);

    size_t smem = (size_t)(S * HSTRIDE + HDIM * EDIM + EDIM) * sizeof(float)
                + (size_t)WARPS * CAP * sizeof(unsigned);
    cudaFuncSetAttribute(embed_kernel,
                         cudaFuncAttributeMaxDynamicSharedMemorySize, (int)smem);

    int dev = 0, sms = 148;
    cudaGetDevice(&dev);
    cudaDeviceGetAttribute(&sms, cudaDevAttrMultiProcessorCount, dev);

    embed_kernel<<<sms, THREADS, smem>>>(m, W2, b2, out, L);
}